// round 8
// baseline (speedup 1.0000x reference)
#include <cuda_runtime.h>

#define NROWS 1024
#define MROWS 1024
#define DIM   512

__device__ float g_hx[NROWS * DIM];
__device__ float g_hy[MROWS * DIM];

typedef unsigned long long u64;

#define ADD2(d, a, b) \
    asm("add.rn.f32x2 %0, %1, %2;" : "=l"(d) : "l"(a), "l"(b))
#define FMA2(d, a, b, c) \
    asm("fma.rn.f32x2 %0, %1, %2, %3;" : "=l"(d) : "l"(a), "l"(b), "l"(c))

__device__ __forceinline__ u64 relu2(u64 s) {
    unsigned int lo, hi;
    asm("mov.b64 {%0,%1}, %2;" : "=r"(lo), "=r"(hi) : "l"(s));
    float f0 = fmaxf(__uint_as_float(lo), 0.0f);
    float f1 = fmaxf(__uint_as_float(hi), 0.0f);
    u64 r;
    asm("mov.b64 %0, {%1,%2};"
        : "=l"(r) : "r"(__float_as_uint(f0)), "r"(__float_as_uint(f1)));
    return r;
}

__device__ __forceinline__ float hsum2(u64 s) {
    unsigned int lo, hi;
    asm("mov.b64 {%0,%1}, %2;" : "=r"(lo), "=r"(hi) : "l"(s));
    return __uint_as_float(lo) + __uint_as_float(hi);
}

// -------------------------------------------------------------------------
// GEMM (R7, unchanged): C[m][n] = sum_k A[m][k]*W[k][n].
// -------------------------------------------------------------------------
__global__ void __launch_bounds__(256, 2) gemm_dual(const float* __restrict__ x,
                                                    const float* __restrict__ y,
                                                    const float* __restrict__ W1) {
    const int z = blockIdx.z;
    const float* __restrict__ A = (z == 0) ? x : y;
    const float* __restrict__ W = W1 + z * DIM * DIM;
    float* __restrict__ C = (z == 0) ? g_hx : g_hy;

    __shared__ float As[2][64][36];
    __shared__ float Bs[2][64][34];

    const int tid = threadIdx.x;
    const int tn = tid & 15;
    const int tm = tid >> 4;
    const int m0 = blockIdx.y * 64;
    const int n0 = blockIdx.x * 64;

    const int ar = tid >> 3;
    const int ac = tid & 7;
    const int wk = tid >> 4;
    const int wc = tid & 15;

    u64 acc[4][4];
#pragma unroll
    for (int i = 0; i < 4; i++)
#pragma unroll
        for (int j = 0; j < 4; j++) acc[i][j] = 0ULL;

    float4 aS[2], wS[2];
#pragma unroll
    for (int it = 0; it < 2; it++) {
        aS[it] = *(const float4*)&A[(m0 + ar + it * 32) * DIM + ac * 4];
        wS[it] = *(const float4*)&W[(wk + it * 16) * DIM + n0 + wc * 4];
    }
#pragma unroll
    for (int it = 0; it < 2; it++) {
        *(float4*)&As[0][ar + it * 32][ac * 4] = aS[it];
        Bs[0][wc * 4 + 0][wk + it * 16] = wS[it].x;
        Bs[0][wc * 4 + 1][wk + it * 16] = wS[it].y;
        Bs[0][wc * 4 + 2][wk + it * 16] = wS[it].z;
        Bs[0][wc * 4 + 3][wk + it * 16] = wS[it].w;
    }
    __syncthreads();

    u64 a2[2][4], b2[2][4];
#pragma unroll
    for (int i = 0; i < 4; i++) a2[0][i] = *(const u64*)&As[0][tm * 4 + i][0];
#pragma unroll
    for (int j = 0; j < 4; j++) b2[0][j] = *(const u64*)&Bs[0][tn + 16 * j][0];

    for (int k0i = 0; k0i < 16; k0i++) {
        const int buf = k0i & 1;
        if (k0i < 15) {
            const int kng = (k0i + 1) * 32;
#pragma unroll
            for (int it = 0; it < 2; it++) {
                aS[it] = *(const float4*)&A[(m0 + ar + it * 32) * DIM + kng + ac * 4];
                wS[it] = *(const float4*)&W[(kng + wk + it * 16) * DIM + n0 + wc * 4];
            }
        }

#pragma unroll
        for (int kk = 0; kk < 32; kk += 2) {
            const int cur = (kk >> 1) & 1;
            const int nxt = cur ^ 1;
            if (kk < 30) {
#pragma unroll
                for (int i = 0; i < 4; i++)
                    a2[nxt][i] = *(const u64*)&As[buf][tm * 4 + i][kk + 2];
#pragma unroll
                for (int j = 0; j < 4; j++)
                    b2[nxt][j] = *(const u64*)&Bs[buf][tn + 16 * j][kk + 2];
            }
#pragma unroll
            for (int i = 0; i < 4; i++)
#pragma unroll
                for (int j = 0; j < 4; j++)
                    FMA2(acc[i][j], a2[cur][i], b2[cur][j], acc[i][j]);
        }

        if (k0i < 15) {
            const int nb = buf ^ 1;
#pragma unroll
            for (int it = 0; it < 2; it++) {
                *(float4*)&As[nb][ar + it * 32][ac * 4] = aS[it];
                Bs[nb][wc * 4 + 0][wk + it * 16] = wS[it].x;
                Bs[nb][wc * 4 + 1][wk + it * 16] = wS[it].y;
                Bs[nb][wc * 4 + 2][wk + it * 16] = wS[it].z;
                Bs[nb][wc * 4 + 3][wk + it * 16] = wS[it].w;
            }
        }
        __syncthreads();
        if (k0i < 15) {
            const int nb = buf ^ 1;
#pragma unroll
            for (int i = 0; i < 4; i++)
                a2[0][i] = *(const u64*)&As[nb][tm * 4 + i][0];
#pragma unroll
            for (int j = 0; j < 4; j++)
                b2[0][j] = *(const u64*)&Bs[nb][tn + 16 * j][0];
        }
    }

#pragma unroll
    for (int i = 0; i < 4; i++)
#pragma unroll
        for (int j = 0; j < 4; j++)
            C[(m0 + tm * 4 + i) * DIM + n0 + tn + 16 * j] = hsum2(acc[i][j]);
}

// -------------------------------------------------------------------------
// Pairwise v2: out[i][j] = sum_d relu(hx[i][d]+hy[j][d]) * w2[d], full d.
// 256 blocks (single resident wave at occupancy 2), 64x64 tile, 4x4/thread.
// d chunks of 32, double-buffered smem with register-staged prefetch:
// 1 sync per chunk, tile-load latency hidden under compute.
// -------------------------------------------------------------------------
__global__ void __launch_bounds__(256, 2) pairwise_kernel(const float* __restrict__ w2,
                                                          float* __restrict__ out) {
    __shared__ float xs[2][64][36];
    __shared__ float ys[2][64][36];
    __shared__ float w2s[DIM];

    const int tid = threadIdx.x;
    const int tx = tid & 15;
    const int ty = tid >> 4;
    const int i0 = blockIdx.y * 64;
    const int j0 = blockIdx.x * 64;

    const int lr = tid >> 3;   // loader row base (0..31), +32 for it=1
    const int lc = tid & 7;    // loader chunk-of-4 (0..7)

    u64 acc[4][4];
#pragma unroll
    for (int i = 0; i < 4; i++)
#pragma unroll
        for (int j = 0; j < 4; j++) acc[i][j] = 0ULL;

    if (tid < 128)
        *(float4*)&w2s[tid * 4] = *(const float4*)&w2[tid * 4];

    float4 sx[2], sy[2];
#pragma unroll
    for (int it = 0; it < 2; it++) {
        sx[it] = *(const float4*)&g_hx[(i0 + lr + it * 32) * DIM + lc * 4];
        sy[it] = *(const float4*)&g_hy[(j0 + lr + it * 32) * DIM + lc * 4];
    }
#pragma unroll
    for (int it = 0; it < 2; it++) {
        *(float4*)&xs[0][lr + it * 32][lc * 4] = sx[it];
        *(float4*)&ys[0][lr + it * 32][lc * 4] = sy[it];
    }
    __syncthreads();

    for (int ch = 0; ch < 16; ch++) {
        const int buf = ch & 1;
        if (ch < 15) {
            const int dg = (ch + 1) * 32;
#pragma unroll
            for (int it = 0; it < 2; it++) {
                sx[it] = *(const float4*)&g_hx[(i0 + lr + it * 32) * DIM + dg + lc * 4];
                sy[it] = *(const float4*)&g_hy[(j0 + lr + it * 32) * DIM + dg + lc * 4];
            }
        }

        const float* __restrict__ w2p = &w2s[ch * 32];
#pragma unroll
        for (int dd = 0; dd < 32; dd += 4) {
            u64 a[4][2], b[4][2];
#pragma unroll
            for (int ti = 0; ti < 4; ti++) {
                ulonglong2 av = *(const ulonglong2*)&xs[buf][ty + 16 * ti][dd];
                a[ti][0] = av.x;
                a[ti][1] = av.y;
            }
#pragma unroll
            for (int tj = 0; tj < 4; tj++) {
                ulonglong2 bv = *(const ulonglong2*)&ys[buf][tx + 16 * tj][dd];
                b[tj][0] = bv.x;
                b[tj][1] = bv.y;
            }
            ulonglong2 wv = *(const ulonglong2*)&w2p[dd];
            u64 w[2];
            w[0] = wv.x;
            w[1] = wv.y;
#pragma unroll
            for (int ti = 0; ti < 4; ti++)
#pragma unroll
                for (int tj = 0; tj < 4; tj++) {
#pragma unroll
                    for (int p = 0; p < 2; p++) {
                        u64 s;
                        ADD2(s, a[ti][p], b[tj][p]);
                        s = relu2(s);
                        FMA2(acc[ti][tj], s, w[p], acc[ti][tj]);
                    }
                }
        }

        if (ch < 15) {
            const int nb = buf ^ 1;
#pragma unroll
            for (int it = 0; it < 2; it++) {
                *(float4*)&xs[nb][lr + it * 32][lc * 4] = sx[it];
                *(float4*)&ys[nb][lr + it * 32][lc * 4] = sy[it];
            }
        }
        __syncthreads();
    }

#pragma unroll
    for (int ti = 0; ti < 4; ti++)
#pragma unroll
        for (int tj = 0; tj < 4; tj++)
            out[(i0 + ty + 16 * ti) * MROWS + j0 + tx + 16 * tj] =
                hsum2(acc[ti][tj]);
}

extern "C" void kernel_launch(void* const* d_in, const int* in_sizes, int n_in,
                              void* d_out, int out_size) {
    const float* x  = (const float*)d_in[0];
    const float* y  = (const float*)d_in[1];
    const float* W1 = (const float*)d_in[2];
    const float* W2 = (const float*)d_in[3];
    float* out = (float*)d_out;

    dim3 ggrid(DIM / 64, NROWS / 64, 2);     // 256 blocks
    gemm_dual<<<ggrid, 256>>>(x, y, W1);

    dim3 pgrid(MROWS / 64, NROWS / 64);      // 256 blocks, single wave
    pairwise_kernel<<<pgrid, 256>>>(W2, out);
}